// round 17
// baseline (speedup 1.0000x reference)
#include <cuda_runtime.h>
#include <math.h>

#define BSZ 8
#define CH  1024
#define TT  1024
#define NH  16
#define HD  64
#define RD  32   // rope dim
#define RH  16   // rope half

// ---------------- scratch (device globals; no allocation allowed) ----------
__device__ float g_p[(size_t)BSZ * CH * TT];   // attn out (tf32-rounded fp32)
__device__ float g_q[(size_t)BSZ * CH * TT];   // [B,H,T,D]
__device__ float g_k[(size_t)BSZ * CH * TT];
__device__ float g_v[(size_t)BSZ * CH * TT];
__device__ float g_xr[(size_t)BSZ * CH * TT];  // tf32-rounded x
__device__ float g_cr[(size_t)BSZ * CH * TT];  // tf32-rounded ctx
__device__ float g_wr[(size_t)4 * CH * CH];    // tf32-rounded Wq,Wk,Wv,Wo

// ---------------------------------------------------------------------------
__device__ __forceinline__ unsigned f2tf32(float x) {
  unsigned r;
  asm("cvt.rna.tf32.f32 %0, %1;" : "=r"(r) : "f"(x));
  return r;
}

__device__ __forceinline__ void mma_tf32(float c[4], unsigned a0, unsigned a1,
                                         unsigned a2, unsigned a3, unsigned b0,
                                         unsigned b1) {
  asm volatile(
      "mma.sync.aligned.m16n8k8.row.col.f32.tf32.tf32.f32 "
      "{%0,%1,%2,%3}, {%4,%5,%6,%7}, {%8,%9}, {%0,%1,%2,%3};"
      : "+f"(c[0]), "+f"(c[1]), "+f"(c[2]), "+f"(c[3])
      : "r"(a0), "r"(a1), "r"(a2), "r"(a3), "r"(b0), "r"(b1));
}

__device__ __forceinline__ void cp16(unsigned saddr, const void* gptr) {
  asm volatile("cp.async.ca.shared.global [%0], [%1], 16;" ::"r"(saddr),
               "l"(gptr));
}

// ---------------------------------------------------------------------------
// Pre-round x, ctx, and the 4 weight matrices to tf32 (stored as fp32 bits).
// grid (2048, 1, 6), 256 threads, grid-stride float4.
// ---------------------------------------------------------------------------
__global__ void __launch_bounds__(256) round6(
    const float* __restrict__ x, const float* __restrict__ ctx,
    const float* __restrict__ Wq, const float* __restrict__ Wk,
    const float* __restrict__ Wv, const float* __restrict__ Wo,
    float* __restrict__ xr, float* __restrict__ cr, float* __restrict__ wr) {
  const int z = blockIdx.z;
  const float* src;
  float* dst;
  size_t n4;
  if (z == 0) {
    src = x; dst = xr; n4 = (size_t)BSZ * CH * TT / 4;
  } else if (z == 1) {
    src = ctx; dst = cr; n4 = (size_t)BSZ * CH * TT / 4;
  } else {
    const float* ws[4] = {Wq, Wk, Wv, Wo};
    src = ws[z - 2];
    dst = wr + (size_t)(z - 2) * CH * CH;
    n4 = (size_t)CH * CH / 4;
  }
  size_t i0 = (size_t)blockIdx.x * blockDim.x + threadIdx.x;
  size_t stride = (size_t)gridDim.x * blockDim.x;
  for (size_t i = i0; i < n4; i += stride) {
    float4 v = ((const float4*)src)[i];
    float4 r;
    r.x = __uint_as_float(f2tf32(v.x));
    r.y = __uint_as_float(f2tf32(v.y));
    r.z = __uint_as_float(f2tf32(v.z));
    r.w = __uint_as_float(f2tf32(v.w));
    ((float4*)dst)[i] = r;
  }
}

// ---------------------------------------------------------------------------
// TF32 GEMM, 3-stage cp.async pipeline. Operands MUST be pre-rounded tf32.
//   acc[m][n] = sum_k W[m][k] * Xb[k][n] + bias[m]
// mode 0: Out[B,C,T]; mode 1: rope+transpose [B,H,T,D]; mode 2: transpose.
// blockIdx.x: n-tile, blockIdx.y: m-tile. 256 thr, warp tile 64x32.
// ---------------------------------------------------------------------------
#define SA (128 * 36)
#define SB (32 * 136)
#define NSTG 3
#define GSMEM (NSTG * (SA + SB) * 4)
#define KT_N (CH / 32)

__device__ __forceinline__ void gemm_body(
    const float* __restrict__ W, const float* __restrict__ Xb,
    const float* __restrict__ bias, float* __restrict__ Out, int mode,
    int bIdx) {
  extern __shared__ unsigned dsm[];
  const unsigned sbase = (unsigned)__cvta_generic_to_shared(dsm);

  const int m0 = blockIdx.y * 128, n0 = blockIdx.x * 128;
  const int tid = threadIdx.x;
  const int warp = tid >> 5, lane = tid & 31;
  const int wm = warp & 1, wn = warp >> 1;
  const int g = lane >> 2, tg = lane & 3;

  // cp.async chunk indices
  const int arow = tid >> 3;         // 0..31 (A row within 32-row pass)
  const int ac4 = (tid & 7) * 4;     // 0..28 (A col, floats)
  const int brow = tid >> 5;         // 0..7  (B row within 8-row pass)
  const int bc4 = (tid & 31) * 4;    // 0..124 (B col, floats)

  float acc[4][4][4];
#pragma unroll
  for (int i = 0; i < 4; i++)
#pragma unroll
    for (int j = 0; j < 4; j++)
#pragma unroll
      for (int r = 0; r < 4; r++) acc[i][j][r] = 0.0f;

#define ISSUE_STAGE(kt)                                                        \
  do {                                                                         \
    const int _k0 = (kt) * 32;                                                 \
    const unsigned _sa = sbase + (((kt) % NSTG) * (SA + SB)) * 4;              \
    const unsigned _sb = _sa + SA * 4;                                         \
    _Pragma("unroll") for (int p = 0; p < 4; p++) {                            \
      cp16(_sa + (((arow + 32 * p) * 36 + ac4) << 2),                          \
           &W[(size_t)(m0 + arow + 32 * p) * CH + _k0 + ac4]);                 \
      cp16(_sb + (((brow + 8 * p) * 136 + bc4) << 2),                          \
           &Xb[(size_t)(_k0 + brow + 8 * p) * TT + n0 + bc4]);                 \
    }                                                                          \
    asm volatile("cp.async.commit_group;");                                    \
  } while (0)

  ISSUE_STAGE(0);
  ISSUE_STAGE(1);

  for (int kt = 0; kt < KT_N; kt++) {
    if (kt + 2 < KT_N)
      asm volatile("cp.async.wait_group 1;");
    else
      asm volatile("cp.async.wait_group 0;");
    __syncthreads();   // stage kt visible to all; all done reading buf (kt+2)%3

    if (kt + 2 < KT_N) ISSUE_STAGE(kt + 2);

    const unsigned* As = dsm + (kt % NSTG) * (SA + SB);
    const unsigned* Bs = As + SA;

#pragma unroll
    for (int ks = 0; ks < 4; ks++) {
      const int kk = ks * 8;
      unsigned a[4][4], b[4][2];
#pragma unroll
      for (int mi = 0; mi < 4; mi++) {
        int row = wm * 64 + mi * 16 + g;
        a[mi][0] = As[row * 36 + kk + tg];
        a[mi][1] = As[(row + 8) * 36 + kk + tg];
        a[mi][2] = As[row * 36 + kk + tg + 4];
        a[mi][3] = As[(row + 8) * 36 + kk + tg + 4];
      }
#pragma unroll
      for (int ni = 0; ni < 4; ni++) {
        int col = wn * 32 + ni * 8 + g;
        b[ni][0] = Bs[(kk + tg) * 136 + col];
        b[ni][1] = Bs[(kk + tg + 4) * 136 + col];
      }
#pragma unroll
      for (int mi = 0; mi < 4; mi++)
#pragma unroll
        for (int ni = 0; ni < 4; ni++)
          mma_tf32(acc[mi][ni], a[mi][0], a[mi][1], a[mi][2], a[mi][3],
                   b[ni][0], b[ni][1]);
    }
    __syncthreads();   // done reading stage kt before it is refilled
  }
#undef ISSUE_STAGE

  // ---- bias ----
#pragma unroll
  for (int mi = 0; mi < 4; mi++) {
    float bv0 = bias[m0 + wm * 64 + mi * 16 + g];
    float bv1 = bias[m0 + wm * 64 + mi * 16 + g + 8];
#pragma unroll
    for (int ni = 0; ni < 4; ni++) {
      acc[mi][ni][0] += bv0; acc[mi][ni][1] += bv0;
      acc[mi][ni][2] += bv1; acc[mi][ni][3] += bv1;
    }
  }

  if (mode == 0) {
    float* Ob = Out + (size_t)bIdx * CH * TT;
#pragma unroll
    for (int mi = 0; mi < 4; mi++) {
      int row = m0 + wm * 64 + mi * 16 + g;
#pragma unroll
      for (int ni = 0; ni < 4; ni++) {
        int col = n0 + wn * 32 + ni * 8 + 2 * tg;
        *(float2*)&Ob[(size_t)row * TT + col] =
            make_float2(acc[mi][ni][0], acc[mi][ni][1]);
        *(float2*)&Ob[(size_t)(row + 8) * TT + col] =
            make_float2(acc[mi][ni][2], acc[mi][ni][3]);
      }
    }
    return;
  }

  if (mode == 1) {
    float th0 = powf(10000.0f, -(2.0f * g) / (float)RD);
    float th1 = powf(10000.0f, -(2.0f * (g + 8)) / (float)RD);
#pragma unroll
    for (int ni = 0; ni < 4; ni++) {
      int t0c = n0 + wn * 32 + ni * 8 + 2 * tg;
#pragma unroll
      for (int j = 0; j < 2; j++) {
        float t = (float)(t0c + j);
        float s, c;
        sincosf(t * th0, &s, &c);
        float x0 = acc[0][ni][j], x1 = acc[1][ni][j];
        acc[0][ni][j] = x0 * c - x1 * s;
        acc[1][ni][j] = x1 * c + x0 * s;
        sincosf(t * th1, &s, &c);
        float y0 = acc[0][ni][2 + j], y1 = acc[1][ni][2 + j];
        acc[0][ni][2 + j] = y0 * c - y1 * s;
        acc[1][ni][2 + j] = y1 * c + y0 * s;
      }
    }
  }

  {
    int head = blockIdx.y * 2 + wm;
    float* Oq = Out + ((size_t)bIdx * NH + head) * TT * 64;
#pragma unroll
    for (int mi = 0; mi < 4; mi++) {
      int d = mi * 16 + g;
#pragma unroll
      for (int ni = 0; ni < 4; ni++) {
        int t = n0 + wn * 32 + ni * 8 + 2 * tg;
        Oq[(size_t)t * 64 + d] = acc[mi][ni][0];
        Oq[(size_t)(t + 1) * 64 + d] = acc[mi][ni][1];
        Oq[(size_t)t * 64 + d + 8] = acc[mi][ni][2];
        Oq[(size_t)(t + 1) * 64 + d + 8] = acc[mi][ni][3];
      }
    }
  }
}

// Merged Q/K/V projection: grid.z = BSZ*3, z = b*3 + {0:K, 1:V, 2:Q}.
__global__ void __launch_bounds__(256) gemm_qkv(
    const float* __restrict__ xr, const float* __restrict__ cr,
    const float* __restrict__ wr, const float* __restrict__ bq,
    const float* __restrict__ bk, const float* __restrict__ bv,
    float* __restrict__ q, float* __restrict__ k, float* __restrict__ v) {
  const int z = blockIdx.z;
  const int b = z / 3, which = z - 3 * b;
  if (which == 0) {
    gemm_body(wr + (size_t)1 * CH * CH, cr + (size_t)b * CH * TT, bk, k, 1, b);
  } else if (which == 1) {
    gemm_body(wr + (size_t)2 * CH * CH, cr + (size_t)b * CH * TT, bv, v, 2, b);
  } else {
    gemm_body(wr + (size_t)0 * CH * CH, xr + (size_t)b * CH * TT, bq, q, 1, b);
  }
}

// Output projection (mode 0), grid.z = B.
__global__ void __launch_bounds__(256) gemm_o(
    const float* __restrict__ wr, const float* __restrict__ X,
    const float* __restrict__ bias, float* __restrict__ Out) {
  gemm_body(wr + (size_t)3 * CH * CH, X + (size_t)blockIdx.z * CH * TT, bias,
            Out, 0, blockIdx.z);
}

// ---------------------------------------------------------------------------
// Tensor-core flash attention (R13/R15 config): 4 warps, 32 q-rows/warp
// (two 16-row m-sets sharing K/V B-fragments), 128 q-rows/CTA, 64-key tiles
// in two 32-key half-passes. Epilogue writes tf32-rounded fp32 (feeds the
// cp.async gemm_o exactly as the old in-GEMM rounding did).
// ---------------------------------------------------------------------------
#define ASTR 68
#define OSTR 136
#define ATT_SMEM ((2 * 64 * ASTR + 128 * ASTR + 1024 + 64) * 4)

__global__ void __launch_bounds__(128) attn_mma(
    const float* __restrict__ Q, const float* __restrict__ K,
    const float* __restrict__ V, const int* __restrict__ mask,
    float* __restrict__ AO) {
  extern __shared__ char smraw[];
  unsigned* Ks = (unsigned*)smraw;            // [64][ASTR]
  unsigned* Vs = Ks + 64 * ASTR;              // [64][ASTR]
  unsigned* Ps = Vs + 64 * ASTR;              // [128][ASTR] (Q then P)
  float* bias_t = (float*)(Ps + 128 * ASTR);  // [1024]
  int* msk = (int*)(bias_t + 1024);           // [64]
  float* Od = (float*)Ks;                     // [64][OSTR] output staging

  const int tid = threadIdx.x;
  const int warp = tid >> 5, lane = tid & 31;
  const int g = lane >> 2, tg = lane & 3;
  const int b = blockIdx.z, h = blockIdx.y, q0 = blockIdx.x * 128;
  const size_t bh = (size_t)b * NH + h;
  const float* Qb = Q + (bh * TT + q0) * 64;
  const float* Kb = K + bh * TT * 64;
  const float* Vb = V + bh * TT * 64;
  const int* mb = mask + (size_t)b * TT;

  for (int i = tid; i < 1024; i += 128) bias_t[i] = -log1pf((float)i);

#pragma unroll
  for (int i = 0; i < 16; i++) {
    int idx = i * 128 + tid;
    int row = idx >> 4, c4 = (idx & 15) * 4;
    float4 v4 = *(const float4*)&Qb[row * 64 + c4];
    uint4 u;
    u.x = f2tf32(v4.x * 0.125f); u.y = f2tf32(v4.y * 0.125f);
    u.z = f2tf32(v4.z * 0.125f); u.w = f2tf32(v4.w * 0.125f);
    *(uint4*)&Ps[row * ASTR + c4] = u;
  }
  __syncthreads();

  unsigned aq[2][8][4];
#pragma unroll
  for (int set = 0; set < 2; set++) {
    int rq = warp * 32 + set * 16 + g;
#pragma unroll
    for (int kc = 0; kc < 8; kc++) {
      aq[set][kc][0] = Ps[rq * ASTR + kc * 8 + tg];
      aq[set][kc][1] = Ps[(rq + 8) * ASTR + kc * 8 + tg];
      aq[set][kc][2] = Ps[rq * ASTR + kc * 8 + tg + 4];
      aq[set][kc][3] = Ps[(rq + 8) * ASTR + kc * 8 + tg + 4];
    }
  }

  float accO[2][8][4];
#pragma unroll
  for (int set = 0; set < 2; set++)
#pragma unroll
    for (int nt = 0; nt < 8; nt++)
#pragma unroll
      for (int i = 0; i < 4; i++) accO[set][nt][i] = 0.0f;
  float mr[2][2] = {{-INFINITY, -INFINITY}, {-INFINITY, -INFINITY}};
  float lr[2][2] = {{0.0f, 0.0f}, {0.0f, 0.0f}};
  int trow[2][2];
#pragma unroll
  for (int set = 0; set < 2; set++) {
    trow[set][0] = q0 + warp * 32 + set * 16 + g;
    trow[set][1] = trow[set][0] + 8;
  }

  for (int k0 = 0; k0 < TT; k0 += 64) {
    __syncthreads();
#pragma unroll
    for (int i = 0; i < 8; i++) {
      int idx = i * 128 + tid;
      int row = idx >> 4, c4 = (idx & 15) * 4;
      float4 kv = *(const float4*)&Kb[(size_t)(k0 + row) * 64 + c4];
      uint4 uk;
      uk.x = f2tf32(kv.x); uk.y = f2tf32(kv.y);
      uk.z = f2tf32(kv.z); uk.w = f2tf32(kv.w);
      *(uint4*)&Ks[row * ASTR + c4] = uk;
      float4 vv = *(const float4*)&Vb[(size_t)(k0 + row) * 64 + c4];
      uint4 uv;
      uv.x = f2tf32(vv.x); uv.y = f2tf32(vv.y);
      uv.z = f2tf32(vv.z); uv.w = f2tf32(vv.w);
      *(uint4*)&Vs[row * ASTR + c4] = uv;
    }
    if (tid < 64) msk[tid] = mb[k0 + tid];
    __syncthreads();

#pragma unroll
    for (int h2 = 0; h2 < 2; h2++) {
      const int kh = h2 * 32;

      float s[2][4][4];
#pragma unroll
      for (int nt = 0; nt < 4; nt++) {
        float c0[4] = {0, 0, 0, 0}, c1[4] = {0, 0, 0, 0};
#pragma unroll
        for (int kc = 0; kc < 8; kc++) {
          unsigned b0 = Ks[(kh + nt * 8 + g) * ASTR + kc * 8 + tg];
          unsigned b1 = Ks[(kh + nt * 8 + g) * ASTR + kc * 8 + tg + 4];
          mma_tf32(c0, aq[0][kc][0], aq[0][kc][1], aq[0][kc][2], aq[0][kc][3],
                   b0, b1);
          mma_tf32(c1, aq[1][kc][0], aq[1][kc][1], aq[1][kc][2], aq[1][kc][3],
                   b0, b1);
        }
        int kl = kh + nt * 8 + 2 * tg;
        int kA = k0 + kl;
        bool z0 = (msk[kl] == 0), z1 = (msk[kl + 1] == 0);
        s[0][nt][0] = z0 ? -10000.0f : c0[0] + bias_t[abs(trow[0][0] - kA)];
        s[0][nt][1] = z1 ? -10000.0f : c0[1] + bias_t[abs(trow[0][0] - kA - 1)];
        s[0][nt][2] = z0 ? -10000.0f : c0[2] + bias_t[abs(trow[0][1] - kA)];
        s[0][nt][3] = z1 ? -10000.0f : c0[3] + bias_t[abs(trow[0][1] - kA - 1)];
        s[1][nt][0] = z0 ? -10000.0f : c1[0] + bias_t[abs(trow[1][0] - kA)];
        s[1][nt][1] = z1 ? -10000.0f : c1[1] + bias_t[abs(trow[1][0] - kA - 1)];
        s[1][nt][2] = z0 ? -10000.0f : c1[2] + bias_t[abs(trow[1][1] - kA)];
        s[1][nt][3] = z1 ? -10000.0f : c1[3] + bias_t[abs(trow[1][1] - kA - 1)];
      }

#pragma unroll
      for (int set = 0; set < 2; set++) {
        float tm0 = -INFINITY, tm1 = -INFINITY;
#pragma unroll
        for (int nt = 0; nt < 4; nt++) {
          tm0 = fmaxf(tm0, fmaxf(s[set][nt][0], s[set][nt][1]));
          tm1 = fmaxf(tm1, fmaxf(s[set][nt][2], s[set][nt][3]));
        }
        tm0 = fmaxf(tm0, __shfl_xor_sync(0xffffffffu, tm0, 1));
        tm0 = fmaxf(tm0, __shfl_xor_sync(0xffffffffu, tm0, 2));
        tm1 = fmaxf(tm1, __shfl_xor_sync(0xffffffffu, tm1, 1));
        tm1 = fmaxf(tm1, __shfl_xor_sync(0xffffffffu, tm1, 2));
        float mn0 = fmaxf(mr[set][0], tm0), mn1 = fmaxf(mr[set][1], tm1);
        float sc0 = __expf(mr[set][0] - mn0), sc1 = __expf(mr[set][1] - mn1);
        mr[set][0] = mn0; mr[set][1] = mn1;

        int rq = warp * 32 + set * 16 + g;
        float ps0 = 0.0f, ps1 = 0.0f;
#pragma unroll
        for (int nt = 0; nt < 4; nt++) {
          int col = kh + nt * 8 + 2 * tg;
          float p0 = __expf(s[set][nt][0] - mn0);
          float p1 = __expf(s[set][nt][1] - mn0);
          float p2 = __expf(s[set][nt][2] - mn1);
          float p3 = __expf(s[set][nt][3] - mn1);
          ps0 += p0 + p1; ps1 += p2 + p3;
          Ps[rq * ASTR + col] = f2tf32(p0);
          Ps[rq * ASTR + col + 1] = f2tf32(p1);
          Ps[(rq + 8) * ASTR + col] = f2tf32(p2);
          Ps[(rq + 8) * ASTR + col + 1] = f2tf32(p3);
        }
        ps0 += __shfl_xor_sync(0xffffffffu, ps0, 1);
        ps0 += __shfl_xor_sync(0xffffffffu, ps0, 2);
        ps1 += __shfl_xor_sync(0xffffffffu, ps1, 1);
        ps1 += __shfl_xor_sync(0xffffffffu, ps1, 2);
        lr[set][0] = lr[set][0] * sc0 + ps0;
        lr[set][1] = lr[set][1] * sc1 + ps1;

#pragma unroll
        for (int nt = 0; nt < 8; nt++) {
          accO[set][nt][0] *= sc0; accO[set][nt][1] *= sc0;
          accO[set][nt][2] *= sc1; accO[set][nt][3] *= sc1;
        }
      }

      __syncwarp();

#pragma unroll
      for (int kc = 0; kc < 4; kc++) {
        int kcol = kh + kc * 8;
        unsigned pa[2][4];
#pragma unroll
        for (int set = 0; set < 2; set++) {
          int rq = warp * 32 + set * 16 + g;
          pa[set][0] = Ps[rq * ASTR + kcol + tg];
          pa[set][1] = Ps[(rq + 8) * ASTR + kcol + tg];
          pa[set][2] = Ps[rq * ASTR + kcol + tg + 4];
          pa[set][3] = Ps[(rq + 8) * ASTR + kcol + tg + 4];
        }
#pragma unroll
        for (int nt = 0; nt < 8; nt++) {
          unsigned b0 = Vs[(kcol + tg) * ASTR + nt * 8 + g];
          unsigned b1 = Vs[(kcol + tg + 4) * ASTR + nt * 8 + g];
          mma_tf32(accO[0][nt], pa[0][0], pa[0][1], pa[0][2], pa[0][3], b0, b1);
          mma_tf32(accO[1][nt], pa[1][0], pa[1][1], pa[1][2], pa[1][3], b0, b1);
        }
      }
    }
  }

  // epilogue: normalize + tf32-round (feeds cp.async gemm_o), write coalesced
  __syncthreads();
#pragma unroll
  for (int set = 0; set < 2; set++) {
    float inv0 = 1.0f / lr[set][0], inv1 = 1.0f / lr[set][1];
    int rq = warp * 32 + set * 16 + g;
#pragma unroll
    for (int nt = 0; nt < 8; nt++) {
      int d = nt * 8 + 2 * tg;
      Od[d * OSTR + rq] = __uint_as_float(f2tf32(accO[set][nt][0] * inv0));
      Od[(d + 1) * OSTR + rq] = __uint_as_float(f2tf32(accO[set][nt][1] * inv0));
      Od[d * OSTR + rq + 8] = __uint_as_float(f2tf32(accO[set][nt][2] * inv1));
      Od[(d + 1) * OSTR + rq + 8] =
          __uint_as_float(f2tf32(accO[set][nt][3] * inv1));
    }
  }
  __syncthreads();
  {
    int d = tid >> 1;
    int c0 = (tid & 1) * 64;
    float* ao = AO + ((size_t)b * CH + (size_t)h * 64 + d) * TT + q0 + c0;
#pragma unroll
    for (int i = 0; i < 16; i++) {
      float4 o4 = *(float4*)&Od[d * OSTR + c0 + i * 4];
      *(float4*)&ao[i * 4] = o4;
    }
  }
}

// ---------------------------------------------------------------------------
extern "C" void kernel_launch(void* const* d_in, const int* in_sizes, int n_in,
                              void* d_out, int out_size) {
  const float* x    = (const float*)d_in[0];
  const float* ctx  = (const float*)d_in[1];
  const int*   mask = (const int*)d_in[2];
  const float* Wq   = (const float*)d_in[3];
  const float* bq   = (const float*)d_in[4];
  const float* Wk   = (const float*)d_in[5];
  const float* bk   = (const float*)d_in[6];
  const float* Wv   = (const float*)d_in[7];
  const float* bv   = (const float*)d_in[8];
  const float* Wo   = (const float*)d_in[9];
  const float* bo   = (const float*)d_in[10];
  float* out = (float*)d_out;

  float *p, *q, *k, *v, *xr, *cr, *wr;
  cudaGetSymbolAddress((void**)&p, g_p);
  cudaGetSymbolAddress((void**)&q, g_q);
  cudaGetSymbolAddress((void**)&k, g_k);
  cudaGetSymbolAddress((void**)&v, g_v);
  cudaGetSymbolAddress((void**)&xr, g_xr);
  cudaGetSymbolAddress((void**)&cr, g_cr);
  cudaGetSymbolAddress((void**)&wr, g_wr);

  cudaFuncSetAttribute(gemm_qkv, cudaFuncAttributeMaxDynamicSharedMemorySize,
                       GSMEM);
  cudaFuncSetAttribute(gemm_o, cudaFuncAttributeMaxDynamicSharedMemorySize,
                       GSMEM);
  cudaFuncSetAttribute(attn_mma, cudaFuncAttributeMaxDynamicSharedMemorySize,
                       ATT_SMEM);

  dim3 rg(2048, 1, 6);
  dim3 gqkv(TT / 128, CH / 128, BSZ * 3);
  dim3 go(TT / 128, CH / 128, BSZ);
  dim3 ag(TT / 128, NH, BSZ);

  round6<<<rg, 256>>>(x, ctx, Wq, Wk, Wv, Wo, xr, cr, wr);
  gemm_qkv<<<gqkv, 256, GSMEM>>>(xr, cr, wr, bq, bk, bv, q, k, v);
  attn_mma<<<ag, 128, ATT_SMEM>>>(q, k, v, mask, p);
  gemm_o<<<go, 256, GSMEM>>>(wr, p, bo, out);
}